// round 13
// baseline (speedup 1.0000x reference)
#include <cuda_runtime.h>
#include <cstdint>

// DigitCaps broadcasted batched matvec:
//   u_hat[b,r,c,o] = sum_i W[r,c,o,i] * x[b,r,i] + bias[o]
// B=512, R=1152, C=10, O=16, I=8, fp32.
//
// R11: single-flush TMA staging. R8 (68.2us, best) is L1-bound on STG.128
// issue (12 cyc x 737K warp-instrs ~= 34us of LSU time). R10 showed grouped
// flushing forces W-row reloads (flushable chunk needs all 10 c's). So:
// R8's compute loop verbatim (W regs loaded once per cp), STS.128 results
// into a full-block 41KB stage (conflict-free: quarter-warp covers banks
// 0..31 exactly once), ONE flush at block end: 16 contiguous 2560B
// cp.async.bulk.shared->global copies (TMA engine, no LSU cost).
// Smem 66.3KB -> 3 CTAs = 12 warps/SM; warps no longer stall on stores.
// Lane = bg(4) x c2(2) x o4(4); warp w = r_local. 4 b's x 2 c's x 4 o's/thr.

#define DC_B 512
#define DC_R 1152
#define DC_C 10
#define DC_O 16
#define DC_I 8

#define RB 4      // r rows per block (one per warp)
#define BT 16     // batch elems per block

#define SW_FLOATS 5760                 // 4r * 10c * 4(o4) rows of 36 floats
#define SX_FLOATS (BT * 36)            // 576
#define SO_FLOATS (BT * RB * 160)      // 10240 floats = 40960 B stage
#define SMEM_BYTES ((SW_FLOATS + SX_FLOATS + SO_FLOATS) * 4)
#define CHUNK_BYTES (RB * 160 * 4)     // 2560 B contiguous per b

__global__ __launch_bounds__(128, 3)
void digitcaps_kernel(const float* __restrict__ x,
                      const float* __restrict__ W,
                      const float* __restrict__ bias,
                      float* __restrict__ out)
{
    extern __shared__ float smem[];
    float* sW = smem;                          // [g][36], g = (r*10+c)*4+o4
    float* sx = smem + SW_FLOATS;              // [b_local][36]
    float* sO = smem + SW_FLOATS + SX_FLOATS;  // [b_local][r_local][160]

    const int tid = threadIdx.x;
    const int r0  = blockIdx.x * RB;
    const int b0  = blockIdx.y * BT;

    // ---- cooperative W load: 4 r rows * 1280 floats = 1280 float4, coalesced ----
    {
        const float4* Wg = reinterpret_cast<const float4*>(
            W + (size_t)r0 * (DC_C * DC_O * DC_I));
#pragma unroll
        for (int q4 = 0; q4 < 10; ++q4) {
            const int q = q4 * 128 + tid;            // float4 index in W tile
            const float4 v = Wg[q];
            const int ih = q & 1;
            const int o  = (q >> 1) & 15;
            const int rc = q >> 5;                   // r_local*10 + c
            const int g  = rc * 4 + (o >> 2);
            *reinterpret_cast<float4*>(sW + g * 36 + (o & 3) * 8 + ih * 4) = v;
        }
    }
    // ---- cooperative x load: 16 b, each b = one 128B line (4r x 8i) ----
    {
        const int b_i = tid >> 3;                    // 0..15
        const int m   = tid & 7;                     // float4 index within line
        const float4 v = *reinterpret_cast<const float4*>(
            x + ((size_t)(b0 + b_i) * DC_R + r0) * DC_I + m * 4);
        *reinterpret_cast<float4*>(sx + b_i * 36 + m * 4) = v;
    }
    __syncthreads();

    const int lane = tid & 31;
    const int w    = tid >> 5;       // warp id == r_local (0..3)
    const int bg   = lane >> 3;      // 0..3 batch group
    const int c2   = (lane >> 2) & 1;
    const int o4   = lane & 3;

    const float4 bb = *reinterpret_cast<const float4*>(bias + o4 * 4);

#pragma unroll
    for (int cp = 0; cp < 5; ++cp) {
        const int c = cp * 2 + c2;
        // W row for (r, c, o4): 8 distinct padded rows per warp, stride 36
        // floats -> conflict-free; 4-way bg broadcast dedups. Loaded ONCE per cp.
        const float* wr = sW + ((w * DC_C + c) * 4 + o4) * 36;
        const float4 w0a = *reinterpret_cast<const float4*>(wr + 0);
        const float4 w0b = *reinterpret_cast<const float4*>(wr + 4);
        const float4 w1a = *reinterpret_cast<const float4*>(wr + 8);
        const float4 w1b = *reinterpret_cast<const float4*>(wr + 12);
        const float4 w2a = *reinterpret_cast<const float4*>(wr + 16);
        const float4 w2b = *reinterpret_cast<const float4*>(wr + 20);
        const float4 w3a = *reinterpret_cast<const float4*>(wr + 24);
        const float4 w3b = *reinterpret_cast<const float4*>(wr + 28);

#pragma unroll
        for (int k = 0; k < 4; ++k) {
            const int bl = k * 4 + bg;               // block-local b
            // broadcast LDS: 4 distinct 16B addrs per instr (dedup'd)
            const float4 va = *reinterpret_cast<const float4*>(sx + bl * 36 + w * 8);
            const float4 vb = *reinterpret_cast<const float4*>(sx + bl * 36 + w * 8 + 4);

            float4 acc;
            acc.x = fmaf(w0a.x, va.x, fmaf(w0a.y, va.y,
                    fmaf(w0a.z, va.z, fmaf(w0a.w, va.w,
                    fmaf(w0b.x, vb.x, fmaf(w0b.y, vb.y,
                    fmaf(w0b.z, vb.z, fmaf(w0b.w, vb.w, bb.x))))))));
            acc.y = fmaf(w1a.x, va.x, fmaf(w1a.y, va.y,
                    fmaf(w1a.z, va.z, fmaf(w1a.w, va.w,
                    fmaf(w1b.x, vb.x, fmaf(w1b.y, vb.y,
                    fmaf(w1b.z, vb.z, fmaf(w1b.w, vb.w, bb.y))))))));
            acc.z = fmaf(w2a.x, va.x, fmaf(w2a.y, va.y,
                    fmaf(w2a.z, va.z, fmaf(w2a.w, va.w,
                    fmaf(w2b.x, vb.x, fmaf(w2b.y, vb.y,
                    fmaf(w2b.z, vb.z, fmaf(w2b.w, vb.w, bb.z))))))));
            acc.w = fmaf(w3a.x, va.x, fmaf(w3a.y, va.y,
                    fmaf(w3a.z, va.z, fmaf(w3a.w, va.w,
                    fmaf(w3b.x, vb.x, fmaf(w3b.y, vb.y,
                    fmaf(w3b.z, vb.z, fmaf(w3b.w, vb.w, bb.w))))))));

            // STS.128 into stage: quarter-warp covers banks 0..31 once.
            float* sp = sO + bl * (RB * 160) + w * 160 + c * DC_O + o4 * 4;
            *reinterpret_cast<float4*>(sp) = acc;
        }
    }
    __syncthreads();   // all STS complete

    // ---- single flush: 16 contiguous 2560B runs via TMA bulk copy ----
    if (tid == 0) {
        asm volatile("fence.proxy.async.shared::cta;" ::: "memory");
        const uint32_t sbase = (uint32_t)__cvta_generic_to_shared(sO);
#pragma unroll
        for (int bi = 0; bi < BT; ++bi) {
            float* dst = out + ((size_t)(b0 + bi) * DC_R + r0) * (DC_C * DC_O);
            asm volatile(
                "cp.async.bulk.global.shared::cta.bulk_group [%0], [%1], %2;"
                :: "l"(dst), "r"(sbase + bi * CHUNK_BYTES),
                   "r"((uint32_t)CHUNK_BYTES)
                : "memory");
        }
        asm volatile("cp.async.bulk.commit_group;" ::: "memory");
        asm volatile("cp.async.bulk.wait_group 0;" ::: "memory");
    }
    __syncthreads();   // smem must stay live until bulk copies complete
}

extern "C" void kernel_launch(void* const* d_in, const int* in_sizes, int n_in,
                              void* d_out, int out_size)
{
    const float* x    = (const float*)d_in[0];  // [B, R, I]
    const float* W    = (const float*)d_in[1];  // [1, R, C, O, I]
    const float* bias = (const float*)d_in[2];  // [O, 1]
    float* out = (float*)d_out;                 // [B, R, C, O, 1]

    cudaFuncSetAttribute(digitcaps_kernel,
                         cudaFuncAttributeMaxDynamicSharedMemorySize, SMEM_BYTES);

    dim3 block(128, 1, 1);
    dim3 grid(DC_R / RB, DC_B / BT, 1);   // (288, 32)
    digitcaps_kernel<<<grid, block, SMEM_BYTES>>>(x, W, bias, out);
}

// round 14
// speedup vs baseline: 1.1684x; 1.1684x over previous
#include <cuda_runtime.h>

// DigitCaps broadcasted batched matvec:
//   u_hat[b,r,c,o] = sum_i W[r,c,o,i] * x[b,r,i] + bias[o]
// B=512, R=1152, C=10, O=16, I=8, fp32.
//
// R12: R8 (68.2us best: x in regs via broadcast LDG, W in padded smem ->
// regs per cp, 4-segment coalesced STG.128) + register diet for 7 CTAs/SM:
//   - all addressing 32-bit (max element index 94.4M < 2^31) -> fewer
//     64-bit address pairs and IMAD chains (alu pipe was 8.4%)
//   - __launch_bounds__(128, 7): 28 warps/SM (vs 24) to overlap the
//     ~56us L1-busy and ~57us DRAM-compulsory floors better.
// TMA store variants (R9/R10/R11) measured worse: stage smem taxes CTAs/SM
// and the flush tail serializes; STG path + max warps wins.
// Lane = bg(4) x c2(2) x o4(4); warp w = r_local. 4 b's x 2 c's x 4 o's/thr.

#define DC_B 512
#define DC_R 1152
#define DC_C 10
#define DC_O 16
#define DC_I 8

#define RB 4     // r rows per block (one per warp)
#define BT 16    // batch elems per block
// smem W: 4r * 10c * 4(o4) rows of 36 floats = 5760 floats (23KB)
#define SW_FLOATS 5760
#define SMEM_BYTES (SW_FLOATS * 4)

__global__ __launch_bounds__(128, 7)
void digitcaps_kernel(const float* __restrict__ x,
                      const float* __restrict__ W,
                      const float* __restrict__ bias,
                      float* __restrict__ out)
{
    extern __shared__ float smem[];
    float* sW = smem;                 // [g][36], g = (r_local*10 + c)*4 + o4

    const unsigned tid = threadIdx.x;
    const unsigned r0  = blockIdx.x * RB;
    const unsigned b0  = blockIdx.y * BT;

    const unsigned lane = tid & 31u;
    const unsigned w    = tid >> 5;      // warp id == r_local (0..3)
    const unsigned bg   = lane >> 3;     // 0..3 batch group
    const unsigned c2   = (lane >> 2) & 1u;
    const unsigned o4   = lane & 3u;

    const unsigned r = r0 + w;

    // ---- x in registers FIRST (long-latency, issue early): this thread's
    //      4 b's (bl = k*4+bg), 8 floats each. Address uniform across the
    //      8 lanes sharing bg -> single-line broadcast LDG.128 x2. ----
    float4 xa[4], xb[4];
#pragma unroll
    for (int k = 0; k < 4; ++k) {
        const unsigned bl = (unsigned)k * 4u + bg;
        const float4* xp = reinterpret_cast<const float4*>(
            x + ((b0 + bl) * (unsigned)DC_R + r) * (unsigned)DC_I);
        xa[k] = xp[0];
        xb[k] = xp[1];
    }

    const float4 bb = *reinterpret_cast<const float4*>(bias + o4 * 4u);

    // ---- cooperative W load: 4 r rows * 1280 floats = 1280 float4, coalesced ----
    {
        const float4* Wg = reinterpret_cast<const float4*>(
            W + r0 * (unsigned)(DC_C * DC_O * DC_I));
#pragma unroll
        for (unsigned q4 = 0; q4 < 10; ++q4) {
            const unsigned q = q4 * 128u + tid;      // float4 index in W tile
            const float4 v = Wg[q];
            // q -> (rc, o, ih): flat = ((rc)*16 + o)*2 + ih
            const unsigned ih = q & 1u;
            const unsigned o  = (q >> 1) & 15u;
            const unsigned rc = q >> 5;              // r_local*10 + c
            const unsigned g  = rc * 4u + (o >> 2);
            *reinterpret_cast<float4*>(sW + g * 36u + (o & 3u) * 8u + ih * 4u) = v;
        }
    }
    __syncthreads();

    // out element offset: ((b*R + r)*C + c)*O + o   (fits in 32 bits)
    const unsigned out_r = r * (unsigned)(DC_C * DC_O) + o4 * 4u;

#pragma unroll
    for (int cp = 0; cp < 5; ++cp) {
        const unsigned c = (unsigned)cp * 2u + c2;
        // W row for (r, c, o4): 32 floats = 4 o * 8 i. 8 distinct padded rows
        // per warp, stride 36 floats -> conflict-free; bg broadcast dedups.
        const float* wr = sW + ((w * (unsigned)DC_C + c) * 4u + o4) * 36u;
        const float4 w0a = *reinterpret_cast<const float4*>(wr + 0);
        const float4 w0b = *reinterpret_cast<const float4*>(wr + 4);
        const float4 w1a = *reinterpret_cast<const float4*>(wr + 8);
        const float4 w1b = *reinterpret_cast<const float4*>(wr + 12);
        const float4 w2a = *reinterpret_cast<const float4*>(wr + 16);
        const float4 w2b = *reinterpret_cast<const float4*>(wr + 20);
        const float4 w3a = *reinterpret_cast<const float4*>(wr + 24);
        const float4 w3b = *reinterpret_cast<const float4*>(wr + 28);

#pragma unroll
        for (int k = 0; k < 4; ++k) {
            const float4 va = xa[k];
            const float4 vb = xb[k];

            float4 acc;
            acc.x = fmaf(w0a.x, va.x, fmaf(w0a.y, va.y,
                    fmaf(w0a.z, va.z, fmaf(w0a.w, va.w,
                    fmaf(w0b.x, vb.x, fmaf(w0b.y, vb.y,
                    fmaf(w0b.z, vb.z, fmaf(w0b.w, vb.w, bb.x))))))));
            acc.y = fmaf(w1a.x, va.x, fmaf(w1a.y, va.y,
                    fmaf(w1a.z, va.z, fmaf(w1a.w, va.w,
                    fmaf(w1b.x, vb.x, fmaf(w1b.y, vb.y,
                    fmaf(w1b.z, vb.z, fmaf(w1b.w, vb.w, bb.y))))))));
            acc.z = fmaf(w2a.x, va.x, fmaf(w2a.y, va.y,
                    fmaf(w2a.z, va.z, fmaf(w2a.w, va.w,
                    fmaf(w2b.x, vb.x, fmaf(w2b.y, vb.y,
                    fmaf(w2b.z, vb.z, fmaf(w2b.w, vb.w, bb.z))))))));
            acc.w = fmaf(w3a.x, va.x, fmaf(w3a.y, va.y,
                    fmaf(w3a.z, va.z, fmaf(w3a.w, va.w,
                    fmaf(w3b.x, vb.x, fmaf(w3b.y, vb.y,
                    fmaf(w3b.z, vb.z, fmaf(w3b.w, vb.w, bb.w))))))));

            const unsigned b = b0 + (unsigned)k * 4u + bg;
            // Per STG warp instr: 4 x 128B contiguous segments (plain store).
            float4* op = reinterpret_cast<float4*>(
                out + b * (unsigned)(DC_R * DC_C * DC_O) + out_r
                    + c * (unsigned)DC_O);
            *op = acc;
        }
    }
}

extern "C" void kernel_launch(void* const* d_in, const int* in_sizes, int n_in,
                              void* d_out, int out_size)
{
    const float* x    = (const float*)d_in[0];  // [B, R, I]
    const float* W    = (const float*)d_in[1];  // [1, R, C, O, I]
    const float* bias = (const float*)d_in[2];  // [O, 1]
    float* out = (float*)d_out;                 // [B, R, C, O, 1]

    cudaFuncSetAttribute(digitcaps_kernel,
                         cudaFuncAttributeMaxDynamicSharedMemorySize, SMEM_BYTES);

    dim3 block(128, 1, 1);
    dim3 grid(DC_R / RB, DC_B / BT, 1);   // (288, 32)
    digitcaps_kernel<<<grid, block, SMEM_BYTES>>>(x, W, bias, out);
}

// round 15
// speedup vs baseline: 1.4341x; 1.2274x over previous
#include <cuda_runtime.h>

// DigitCaps broadcasted batched matvec:
//   u_hat[b,r,c,o] = sum_i W[r,c,o,i] * x[b,r,i] + bias[o]
// B=512, R=1152, C=10, O=16, I=8, fp32.
//
// R13: R8 dataflow (best, 68.2us) with an o-row-major inner loop to shrink
// the live register set: per cp, hold acc[k] (16 regs) + ONE W o-row pair
// (8 regs) instead of all 8 W float4s (32 regs). Peak live ~70 regs ->
// __launch_bounds__(128,7) fits WITHOUT spills (R12 showed cap-7 with the
// k-major loop spills 2-3 regs -> +70MB DRAM). FMA chains are expression-
// identical (same seed bias, same i-order) -> bit-identical results.
// Same traffic as R8 in every term; only W-reg lifetime changes.
// Lane = bg(4) x c2(2) x o4(4); warp w = r_local. 4 b's x 2 c's x 4 o's/thr.

#define DC_B 512
#define DC_R 1152
#define DC_C 10
#define DC_O 16
#define DC_I 8

#define RB 4     // r rows per block (one per warp)
#define BT 16    // batch elems per block
// smem W: 4r * 10c * 4(o4) rows of 36 floats = 5760 floats (23KB)
#define SW_FLOATS 5760
#define SMEM_BYTES (SW_FLOATS * 4)

// One o-row FMA chain: component 'comp' of acc[k] for W row pair (wa, wb).
#define OROW_CHAIN(accv, comp, wa, wb, va, vb, biasv)                      \
    (accv).comp = fmaf((wa).x, (va).x, fmaf((wa).y, (va).y,                \
                  fmaf((wa).z, (va).z, fmaf((wa).w, (va).w,                \
                  fmaf((wb).x, (vb).x, fmaf((wb).y, (vb).y,                \
                  fmaf((wb).z, (vb).z, fmaf((wb).w, (vb).w, (biasv)))))))))

__global__ __launch_bounds__(128, 7)
void digitcaps_kernel(const float* __restrict__ x,
                      const float* __restrict__ W,
                      const float* __restrict__ bias,
                      float* __restrict__ out)
{
    extern __shared__ float smem[];
    float* sW = smem;                 // [g][36], g = (r_local*10 + c)*4 + o4

    const unsigned tid = threadIdx.x;
    const unsigned r0  = blockIdx.x * RB;
    const unsigned b0  = blockIdx.y * BT;

    // ---- cooperative W load: 4 r rows * 1280 floats = 1280 float4, coalesced ----
    {
        const float4* Wg = reinterpret_cast<const float4*>(
            W + r0 * (unsigned)(DC_C * DC_O * DC_I));
#pragma unroll
        for (unsigned q4 = 0; q4 < 10; ++q4) {
            const unsigned q = q4 * 128u + tid;      // float4 index in W tile
            const float4 v = Wg[q];
            // q -> (rc, o, ih): flat = ((rc)*16 + o)*2 + ih
            const unsigned ih = q & 1u;
            const unsigned o  = (q >> 1) & 15u;
            const unsigned rc = q >> 5;              // r_local*10 + c
            const unsigned g  = rc * 4u + (o >> 2);
            *reinterpret_cast<float4*>(sW + g * 36u + (o & 3u) * 8u + ih * 4u) = v;
        }
    }

    const unsigned lane = tid & 31u;
    const unsigned w    = tid >> 5;      // warp id == r_local (0..3)
    const unsigned bg   = lane >> 3;     // 0..3 batch group
    const unsigned c2   = (lane >> 2) & 1u;
    const unsigned o4   = lane & 3u;

    const unsigned r = r0 + w;

    // ---- x in registers: this thread's 4 b's (bl = k*4+bg), 8 floats each.
    //      Address uniform across the 8 lanes sharing bg -> broadcast LDG. ----
    float4 xa[4], xb[4];
#pragma unroll
    for (int k = 0; k < 4; ++k) {
        const unsigned bl = (unsigned)k * 4u + bg;
        const float4* xp = reinterpret_cast<const float4*>(
            x + ((b0 + bl) * (unsigned)DC_R + r) * (unsigned)DC_I);
        xa[k] = xp[0];
        xb[k] = xp[1];
    }

    const float4 bb = *reinterpret_cast<const float4*>(bias + o4 * 4u);

    __syncthreads();

    // out element offset: ((b*R + r)*C + c)*O + o  (fits in 32 bits)
    const unsigned out_r = r * (unsigned)(DC_C * DC_O) + o4 * 4u;

#pragma unroll
    for (int cp = 0; cp < 5; ++cp) {
        const unsigned c = (unsigned)cp * 2u + c2;
        // W rows for (r, c, o4): 8 distinct padded smem rows per warp,
        // stride 36 floats -> conflict-free; bg 4-way broadcast dedups.
        const float* wr = sW + ((w * (unsigned)DC_C + c) * 4u + o4) * 36u;

        float4 acc0, acc1, acc2, acc3;

        // o-row 0: only (wa, wb) live among W values
        {
            const float4 wa = *reinterpret_cast<const float4*>(wr + 0);
            const float4 wb = *reinterpret_cast<const float4*>(wr + 4);
            OROW_CHAIN(acc0, x, wa, wb, xa[0], xb[0], bb.x);
            OROW_CHAIN(acc1, x, wa, wb, xa[1], xb[1], bb.x);
            OROW_CHAIN(acc2, x, wa, wb, xa[2], xb[2], bb.x);
            OROW_CHAIN(acc3, x, wa, wb, xa[3], xb[3], bb.x);
        }
        // o-row 1
        {
            const float4 wa = *reinterpret_cast<const float4*>(wr + 8);
            const float4 wb = *reinterpret_cast<const float4*>(wr + 12);
            OROW_CHAIN(acc0, y, wa, wb, xa[0], xb[0], bb.y);
            OROW_CHAIN(acc1, y, wa, wb, xa[1], xb[1], bb.y);
            OROW_CHAIN(acc2, y, wa, wb, xa[2], xb[2], bb.y);
            OROW_CHAIN(acc3, y, wa, wb, xa[3], xb[3], bb.y);
        }
        // o-row 2
        {
            const float4 wa = *reinterpret_cast<const float4*>(wr + 16);
            const float4 wb = *reinterpret_cast<const float4*>(wr + 20);
            OROW_CHAIN(acc0, z, wa, wb, xa[0], xb[0], bb.z);
            OROW_CHAIN(acc1, z, wa, wb, xa[1], xb[1], bb.z);
            OROW_CHAIN(acc2, z, wa, wb, xa[2], xb[2], bb.z);
            OROW_CHAIN(acc3, z, wa, wb, xa[3], xb[3], bb.z);
        }
        // o-row 3
        {
            const float4 wa = *reinterpret_cast<const float4*>(wr + 24);
            const float4 wb = *reinterpret_cast<const float4*>(wr + 28);
            OROW_CHAIN(acc0, w, wa, wb, xa[0], xb[0], bb.w);
            OROW_CHAIN(acc1, w, wa, wb, xa[1], xb[1], bb.w);
            OROW_CHAIN(acc2, w, wa, wb, xa[2], xb[2], bb.w);
            OROW_CHAIN(acc3, w, wa, wb, xa[3], xb[3], bb.w);
        }

        // Stores: per STG warp instr 4 x 128B contiguous segments.
        const unsigned obase = out_r + c * (unsigned)DC_O;
        {
            const unsigned b = b0 + 0u * 4u + bg;
            *reinterpret_cast<float4*>(
                out + b * (unsigned)(DC_R * DC_C * DC_O) + obase) = acc0;
        }
        {
            const unsigned b = b0 + 1u * 4u + bg;
            *reinterpret_cast<float4*>(
                out + b * (unsigned)(DC_R * DC_C * DC_O) + obase) = acc1;
        }
        {
            const unsigned b = b0 + 2u * 4u + bg;
            *reinterpret_cast<float4*>(
                out + b * (unsigned)(DC_R * DC_C * DC_O) + obase) = acc2;
        }
        {
            const unsigned b = b0 + 3u * 4u + bg;
            *reinterpret_cast<float4*>(
                out + b * (unsigned)(DC_R * DC_C * DC_O) + obase) = acc3;
        }
    }
}

extern "C" void kernel_launch(void* const* d_in, const int* in_sizes, int n_in,
                              void* d_out, int out_size)
{
    const float* x    = (const float*)d_in[0];  // [B, R, I]
    const float* W    = (const float*)d_in[1];  // [1, R, C, O, I]
    const float* bias = (const float*)d_in[2];  // [O, 1]
    float* out = (float*)d_out;                 // [B, R, C, O, 1]

    cudaFuncSetAttribute(digitcaps_kernel,
                         cudaFuncAttributeMaxDynamicSharedMemorySize, SMEM_BYTES);

    dim3 block(128, 1, 1);
    dim3 grid(DC_R / RB, DC_B / BT, 1);   // (288, 32)
    digitcaps_kernel<<<grid, block, SMEM_BYTES>>>(x, W, bias, out);
}

// round 16
// speedup vs baseline: 1.4481x; 1.0098x over previous
#include <cuda_runtime.h>

// DigitCaps broadcasted batched matvec:
//   u_hat[b,r,c,o] = sum_i W[r,c,o,i] * x[b,r,i] + bias[o]
// B=512, R=1152, C=10, O=16, I=8, fp32.
//
// R14: R13 (66.3us champion: o-row-major inner loop, 72 regs, 7 CTAs/SM)
// with a cheaper x path. Calibrated L1 model (fits 82% busy to ~5%):
// STG 8.8M + LDS 2.9M + LDG 2.6M + STS 1.5M SM-cyc. The x broadcast-LDG
// term (8 instrs/thread x ~4cyc = 1.2M) becomes 2 coop LDG.128 + 8
// PROLOGUE-only LDS.128 (~0.5M): each x 128B line ([b][4r x 8i]) is read
// exactly once chip-wide, and the long-latency LDG leaves the per-warp
// critical path. Hot loop is untouched (in-loop smem x was R7's mistake;
// this is prologue-to-registers only).
// Lane = bg(4) x c2(2) x o4(4); warp w = r_local. 4 b's x 2 c's x 4 o's/thr.

#define DC_B 512
#define DC_R 1152
#define DC_C 10
#define DC_O 16
#define DC_I 8

#define RB 4     // r rows per block (one per warp)
#define BT 16    // batch elems per block
// smem W: 4r * 10c * 4(o4) rows of 36 floats = 5760 floats (23KB)
// smem x: 16 b * 36 floats (32 data + 4 pad)  =  576 floats (2.3KB)
#define SW_FLOATS 5760
#define SX_FLOATS 576
#define SMEM_BYTES ((SW_FLOATS + SX_FLOATS) * 4)

// One o-row FMA chain: component 'comp' of acc[k] for W row pair (wa, wb).
#define OROW_CHAIN(accv, comp, wa, wb, va, vb, biasv)                      \
    (accv).comp = fmaf((wa).x, (va).x, fmaf((wa).y, (va).y,                \
                  fmaf((wa).z, (va).z, fmaf((wa).w, (va).w,                \
                  fmaf((wb).x, (vb).x, fmaf((wb).y, (vb).y,                \
                  fmaf((wb).z, (vb).z, fmaf((wb).w, (vb).w, (biasv)))))))))

__global__ __launch_bounds__(128, 7)
void digitcaps_kernel(const float* __restrict__ x,
                      const float* __restrict__ W,
                      const float* __restrict__ bias,
                      float* __restrict__ out)
{
    extern __shared__ float smem[];
    float* sW = smem;                 // [g][36], g = (r_local*10 + c)*4 + o4
    float* sx = smem + SW_FLOATS;     // [b_local][36]: 4r x 8i + pad

    const unsigned tid = threadIdx.x;
    const unsigned r0  = blockIdx.x * RB;
    const unsigned b0  = blockIdx.y * BT;

    // ---- cooperative x load: 16 b, each b = exactly one 128B line (4r x 8i),
    //      one float4 per thread, perfectly coalesced, read once chip-wide ----
    {
        const unsigned b_i = tid >> 3;               // 0..15
        const unsigned m   = tid & 7u;               // float4 index within line
        const float4 v = *reinterpret_cast<const float4*>(
            x + ((b0 + b_i) * (unsigned)DC_R + r0) * (unsigned)DC_I + m * 4u);
        *reinterpret_cast<float4*>(sx + b_i * 36u + m * 4u) = v;
    }

    // ---- cooperative W load: 4 r rows * 1280 floats = 1280 float4, coalesced ----
    {
        const float4* Wg = reinterpret_cast<const float4*>(
            W + r0 * (unsigned)(DC_C * DC_O * DC_I));
#pragma unroll
        for (unsigned q4 = 0; q4 < 10; ++q4) {
            const unsigned q = q4 * 128u + tid;      // float4 index in W tile
            const float4 v = Wg[q];
            // q -> (rc, o, ih): flat = ((rc)*16 + o)*2 + ih
            const unsigned ih = q & 1u;
            const unsigned o  = (q >> 1) & 15u;
            const unsigned rc = q >> 5;              // r_local*10 + c
            const unsigned g  = rc * 4u + (o >> 2);
            *reinterpret_cast<float4*>(sW + g * 36u + (o & 3u) * 8u + ih * 4u) = v;
        }
    }

    const unsigned lane = tid & 31u;
    const unsigned w    = tid >> 5;      // warp id == r_local (0..3)
    const unsigned bg   = lane >> 3;     // 0..3 batch group
    const unsigned c2   = (lane >> 2) & 1u;
    const unsigned o4   = lane & 3u;

    const unsigned r = r0 + w;

    const float4 bb = *reinterpret_cast<const float4*>(bias + o4 * 4u);

    __syncthreads();

    // ---- x to registers (PROLOGUE only): 8 LDS.128, 4 distinct addrs each ----
    float4 xa[4], xb[4];
#pragma unroll
    for (int k = 0; k < 4; ++k) {
        const unsigned bl = (unsigned)k * 4u + bg;
        xa[k] = *reinterpret_cast<const float4*>(sx + bl * 36u + w * 8u);
        xb[k] = *reinterpret_cast<const float4*>(sx + bl * 36u + w * 8u + 4u);
    }

    // out element offset: ((b*R + r)*C + c)*O + o  (fits in 32 bits)
    const unsigned out_r = r * (unsigned)(DC_C * DC_O) + o4 * 4u;

#pragma unroll
    for (int cp = 0; cp < 5; ++cp) {
        const unsigned c = (unsigned)cp * 2u + c2;
        // W rows for (r, c, o4): 8 distinct padded smem rows per warp,
        // stride 36 floats -> conflict-free; bg 4-way broadcast dedups.
        const float* wr = sW + ((w * (unsigned)DC_C + c) * 4u + o4) * 36u;

        float4 acc0, acc1, acc2, acc3;

        // o-row 0: only (wa, wb) live among W values
        {
            const float4 wa = *reinterpret_cast<const float4*>(wr + 0);
            const float4 wb = *reinterpret_cast<const float4*>(wr + 4);
            OROW_CHAIN(acc0, x, wa, wb, xa[0], xb[0], bb.x);
            OROW_CHAIN(acc1, x, wa, wb, xa[1], xb[1], bb.x);
            OROW_CHAIN(acc2, x, wa, wb, xa[2], xb[2], bb.x);
            OROW_CHAIN(acc3, x, wa, wb, xa[3], xb[3], bb.x);
        }
        // o-row 1
        {
            const float4 wa = *reinterpret_cast<const float4*>(wr + 8);
            const float4 wb = *reinterpret_cast<const float4*>(wr + 12);
            OROW_CHAIN(acc0, y, wa, wb, xa[0], xb[0], bb.y);
            OROW_CHAIN(acc1, y, wa, wb, xa[1], xb[1], bb.y);
            OROW_CHAIN(acc2, y, wa, wb, xa[2], xb[2], bb.y);
            OROW_CHAIN(acc3, y, wa, wb, xa[3], xb[3], bb.y);
        }
        // o-row 2
        {
            const float4 wa = *reinterpret_cast<const float4*>(wr + 16);
            const float4 wb = *reinterpret_cast<const float4*>(wr + 20);
            OROW_CHAIN(acc0, z, wa, wb, xa[0], xb[0], bb.z);
            OROW_CHAIN(acc1, z, wa, wb, xa[1], xb[1], bb.z);
            OROW_CHAIN(acc2, z, wa, wb, xa[2], xb[2], bb.z);
            OROW_CHAIN(acc3, z, wa, wb, xa[3], xb[3], bb.z);
        }
        // o-row 3
        {
            const float4 wa = *reinterpret_cast<const float4*>(wr + 24);
            const float4 wb = *reinterpret_cast<const float4*>(wr + 28);
            OROW_CHAIN(acc0, w, wa, wb, xa[0], xb[0], bb.w);
            OROW_CHAIN(acc1, w, wa, wb, xa[1], xb[1], bb.w);
            OROW_CHAIN(acc2, w, wa, wb, xa[2], xb[2], bb.w);
            OROW_CHAIN(acc3, w, wa, wb, xa[3], xb[3], bb.w);
        }

        // Stores: per STG warp instr 4 x 128B contiguous segments.
        const unsigned obase = out_r + c * (unsigned)DC_O;
        {
            const unsigned b = b0 + 0u * 4u + bg;
            *reinterpret_cast<float4*>(
                out + b * (unsigned)(DC_R * DC_C * DC_O) + obase) = acc0;
        }
        {
            const unsigned b = b0 + 1u * 4u + bg;
            *reinterpret_cast<float4*>(
                out + b * (unsigned)(DC_R * DC_C * DC_O) + obase) = acc1;
        }
        {
            const unsigned b = b0 + 2u * 4u + bg;
            *reinterpret_cast<float4*>(
                out + b * (unsigned)(DC_R * DC_C * DC_O) + obase) = acc2;
        }
        {
            const unsigned b = b0 + 3u * 4u + bg;
            *reinterpret_cast<float4*>(
                out + b * (unsigned)(DC_R * DC_C * DC_O) + obase) = acc3;
        }
    }
}

extern "C" void kernel_launch(void* const* d_in, const int* in_sizes, int n_in,
                              void* d_out, int out_size)
{
    const float* x    = (const float*)d_in[0];  // [B, R, I]
    const float* W    = (const float*)d_in[1];  // [1, R, C, O, I]
    const float* bias = (const float*)d_in[2];  // [O, 1]
    float* out = (float*)d_out;                 // [B, R, C, O, 1]

    cudaFuncSetAttribute(digitcaps_kernel,
                         cudaFuncAttributeMaxDynamicSharedMemorySize, SMEM_BYTES);

    dim3 block(128, 1, 1);
    dim3 grid(DC_R / RB, DC_B / BT, 1);   // (288, 32)
    digitcaps_kernel<<<grid, block, SMEM_BYTES>>>(x, W, bias, out);
}